// round 15
// baseline (speedup 1.0000x reference)
#include <cuda_runtime.h>
#include <math.h>

// D_MODEL=300, L=512, B=512, OUT=4.
// diag[e,i] = fmap[i,i,e] = sum_l e2[i,l,i] * e1[i,l,e], i in [0,300)
//   = scale * sum_l s[i,l]*emb1[x1[i,l]][e]   (gather tasks)
//   +         sum_l s[i,l]*pe[l][e]           (gemm tasks)
// with s[i,l] = emb2[x2[i,l]][i]*scale + pe[l][i].
// SINGLE persistent kernel: 148 blocks x 256 threads (2 x 128-thread lanes),
// phases separated by a hand-rolled grid barrier (deadlock-free: 1 block/SM
// guaranteed resident). All accumulation via atomicAdd into one buffer.

#define D     300
#define LSEQ  512
#define OUTC  4
#define CHUNK 128
#define NBLK  148
#define NTHR  256
#define NLANE (NBLK * 2)          // 296 lanes
#define NGATH (4 * D)             // 1200 gather tasks (i, l-chunk of 128)
#define NGEMM 800                 // 10 x 10 x 8 gemm tasks (K=64)
#define NP1   (NGATH + NGEMM)     // 2000
#define NF1   500                 // 10 x 10 x 5 fc1 tasks (K=60)
#define KT1   60

__device__ float g_pe[LSEQ * D];      // [l][d]
__device__ float g_s[D * LSEQ];       // [i][l]
__device__ float g_acc[2 * D * D];    // [0:D*D) diag [e][i]; [D*D:) hidden [e][j]
__device__ int   g_count = 0;         // grid barrier counter
__device__ int   g_gen   = 0;         // grid barrier generation (monotonic)

__device__ __forceinline__ void grid_sync() {
    __threadfence();
    __syncthreads();
    if (threadIdx.x == 0) {
        int gen = *(volatile int*)&g_gen;
        if (atomicAdd(&g_count, 1) == NBLK - 1) {
            atomicExch(&g_count, 0);
            __threadfence();
            atomicAdd(&g_gen, 1);
        } else {
            while (*(volatile int*)&g_gen == gen) { }
        }
        __threadfence();
    }
    __syncthreads();
}

struct __align__(16) LaneSmem {
    union {
        struct { float st[64][34]; float pe[64][36]; } gm;   // gemm tiles
        struct { float s[CHUNK]; int r1[CHUNK]; } ga;        // gather stage
        struct { float a[KT1][36]; float b[KT1][36]; } fc;   // fc1 tiles
        float red[4][OUTC];                                  // fc2 reduce
    };
};

#define LBAR(id) asm volatile("bar.sync %0, 128;" :: "r"(id))

__global__ __launch_bounds__(NTHR) void matposer_kernel(
    const int*   __restrict__ x1,
    const int*   __restrict__ x2,
    const float* __restrict__ emb1,
    const float* __restrict__ emb2,
    const float* __restrict__ w1,
    const float* __restrict__ b1,
    const float* __restrict__ w2,
    const float* __restrict__ b2,
    float*       __restrict__ out)
{
    __shared__ LaneSmem lanes[2];

    const int tid   = threadIdx.x;
    const int lane  = tid >> 7;           // 0 / 1
    const int ltid  = tid & 127;
    const int lid   = blockIdx.x * 2 + lane;   // 0..295
    const int barid = lane + 1;           // named barriers 1, 2
    const float scale = 17.320508075688775f;   // sqrt(300)
    const float coef  = -9.210340371976184f / (float)D;   // -ln(10000)/300
    LaneSmem* L = &lanes[lane];

    // ---------------- Phase 0: zero acc, build pe and s --------------------
    {
        const int gid    = blockIdx.x * NTHR + tid;
        const int stride = NBLK * NTHR;
        for (int idx = gid; idx < (2 * D * D) / 4; idx += stride)
            reinterpret_cast<float4*>(g_acc)[idx] = make_float4(0.f, 0.f, 0.f, 0.f);
        for (int idx = gid; idx < LSEQ * D; idx += stride) {
            int l = idx / D, d = idx % D;
            float divv = expf((float)(2 * (d >> 1)) * coef);
            float ang  = (float)l * divv;
            g_pe[idx] = (d & 1) ? cosf(ang) : sinf(ang);
        }
        for (int idx = gid; idx < D * LSEQ; idx += stride) {
            int i = idx >> 9, l = idx & (LSEQ - 1);
            float divv = expf((float)(2 * (i >> 1)) * coef);
            float ang  = (float)l * divv;
            float pev  = (i & 1) ? cosf(ang) : sinf(ang);
            g_s[idx] = fmaf(emb2[x2[idx] * D + i], scale, pev);
        }
    }
    grid_sync();

    // ---------------- Phase 1: diag = gather + gemm tasks ------------------
    // 2000 tasks interleaved 3 gather : 2 gemm (NLANE=296, 296%5=1 -> each
    // lane cycles through both roles).
    for (int t = lid; t < NP1; t += NLANE) {
        int grpq = t / 5, r = t % 5;
        if (r < 3) {
            // ----- gather task: (i, chunk) -----
            int gi    = grpq * 3 + r;          // 0..1199
            int i     = gi % D;
            int cb    = (gi / D) * CHUNK;      // chunk base
            LBAR(barid);                       // protect smem reuse
            L->ga.s[ltid]  = g_s[i * LSEQ + cb + ltid];
            L->ga.r1[ltid] = x1[i * LSEQ + cb + ltid] * D;
            LBAR(barid);
            float a0 = 0.f, a1 = 0.f, a2 = 0.f;
            const bool h3 = (ltid < D - 256);  // ltid < 44
            #pragma unroll 8
            for (int l = 0; l < CHUNK; ++l) {
                float sv = L->ga.s[l];
                const float* row = emb1 + L->ga.r1[l];
                a0 = fmaf(sv, row[ltid], a0);
                a1 = fmaf(sv, row[ltid + 128], a1);
                if (h3) a2 = fmaf(sv, row[ltid + 256], a2);
            }
            atomicAdd(&g_acc[ltid * D + i], scale * a0);
            atomicAdd(&g_acc[(ltid + 128) * D + i], scale * a1);
            if (h3) atomicAdd(&g_acc[(ltid + 256) * D + i], scale * a2);
        } else {
            // ----- gemm task: 32e x 32i, K=64 window -----
            int mi = grpq * 2 + (r - 3);       // 0..799
            const int e0 = (mi % 10) * 32;
            const int i0 = ((mi / 10) % 10) * 32;
            const int kb = (mi / 100) * 64;
            const int tx = ltid & 15;          // i pair
            const int ty = ltid >> 4;          // e quad
            LBAR(barid);
            // stage s transposed: 32 i-rows x 64 k
            #pragma unroll
            for (int q = 0; q < 4; ++q) {
                int idx = ltid + q * 128;      // 0..511
                int row = idx >> 4;            // i_local 0..31
                int kk  = (idx & 15) * 4;
                float4 v = make_float4(0.f, 0.f, 0.f, 0.f);
                int ii = i0 + row;
                if (ii < D)
                    v = *reinterpret_cast<const float4*>(g_s + ii * LSEQ + kb + kk);
                L->gm.st[kk][row] = v.x; L->gm.st[kk + 1][row] = v.y;
                L->gm.st[kk + 2][row] = v.z; L->gm.st[kk + 3][row] = v.w;
            }
            // stage pe: 64 k-rows x 32 e
            #pragma unroll
            for (int q = 0; q < 4; ++q) {
                int idx = ltid + q * 128;
                int row = idx >> 3;            // k_local 0..63
                int cc  = (idx & 7) * 4;
                int e   = e0 + cc;
                float4 v = make_float4(0.f, 0.f, 0.f, 0.f);
                if (e <= D - 4)
                    v = *reinterpret_cast<const float4*>(g_pe + (kb + row) * D + e);
                *reinterpret_cast<float4*>(&L->gm.pe[row][cc]) = v;
            }
            LBAR(barid);
            float acc0[4] = {0.f, 0.f, 0.f, 0.f};
            float acc1[4] = {0.f, 0.f, 0.f, 0.f};
            #pragma unroll 4
            for (int k = 0; k < 64; ++k) {
                float2 sv = *reinterpret_cast<const float2*>(&L->gm.st[k][2 * tx]);
                float4 pv = *reinterpret_cast<const float4*>(&L->gm.pe[k][4 * ty]);
                acc0[0] = fmaf(sv.x, pv.x, acc0[0]);
                acc0[1] = fmaf(sv.x, pv.y, acc0[1]);
                acc0[2] = fmaf(sv.x, pv.z, acc0[2]);
                acc0[3] = fmaf(sv.x, pv.w, acc0[3]);
                acc1[0] = fmaf(sv.y, pv.x, acc1[0]);
                acc1[1] = fmaf(sv.y, pv.y, acc1[1]);
                acc1[2] = fmaf(sv.y, pv.z, acc1[2]);
                acc1[3] = fmaf(sv.y, pv.w, acc1[3]);
            }
            const int ip = i0 + 2 * tx;
            const int e  = e0 + 4 * ty;
            if (ip < D) {
                #pragma unroll
                for (int u = 0; u < 4; ++u) {
                    if (e + u < D) {
                        atomicAdd(&g_acc[(e + u) * D + ip], acc0[u]);
                        atomicAdd(&g_acc[(e + u) * D + ip + 1], acc1[u]);
                    }
                }
            }
        }
    }
    grid_sync();

    // ---------------- Phase 2: fc1 (hidden = diag . w1^T) ------------------
    for (int t = lid; t < NF1; t += NLANE) {
        const int j0 = (t % 10) * 32;
        const int e0 = ((t / 10) % 10) * 32;
        const int kb = (t / 100) * KT1;
        const int tx = ltid & 15;
        const int ty = ltid >> 4;
        LBAR(barid);
        for (int idx = ltid; idx < 32 * 15; idx += 128) {
            int row = idx / 15;
            int kk  = (idx % 15) * 4;
            int k   = kb + kk;                 // <= 299
            float4 va = make_float4(0.f, 0.f, 0.f, 0.f);
            float4 vb = va;
            if (e0 + row < D)
                va = *reinterpret_cast<const float4*>(g_acc + (e0 + row) * D + k);
            if (j0 + row < D)
                vb = *reinterpret_cast<const float4*>(w1 + (j0 + row) * D + k);
            L->fc.a[kk][row] = va.x; L->fc.a[kk + 1][row] = va.y;
            L->fc.a[kk + 2][row] = va.z; L->fc.a[kk + 3][row] = va.w;
            L->fc.b[kk][row] = vb.x; L->fc.b[kk + 1][row] = vb.y;
            L->fc.b[kk + 2][row] = vb.z; L->fc.b[kk + 3][row] = vb.w;
        }
        LBAR(barid);
        float acc0[4] = {0.f, 0.f, 0.f, 0.f};
        float acc1[4] = {0.f, 0.f, 0.f, 0.f};
        #pragma unroll 6
        for (int k = 0; k < KT1; ++k) {
            float4 a = *reinterpret_cast<const float4*>(&L->fc.a[k][4 * ty]);
            float2 b = *reinterpret_cast<const float2*>(&L->fc.b[k][2 * tx]);
            acc0[0] = fmaf(b.x, a.x, acc0[0]);
            acc0[1] = fmaf(b.x, a.y, acc0[1]);
            acc0[2] = fmaf(b.x, a.z, acc0[2]);
            acc0[3] = fmaf(b.x, a.w, acc0[3]);
            acc1[0] = fmaf(b.y, a.x, acc1[0]);
            acc1[1] = fmaf(b.y, a.y, acc1[1]);
            acc1[2] = fmaf(b.y, a.z, acc1[2]);
            acc1[3] = fmaf(b.y, a.w, acc1[3]);
        }
        const int jp = j0 + 2 * tx;
        const int e  = e0 + 4 * ty;
        if (jp < D) {
            #pragma unroll
            for (int u = 0; u < 4; ++u) {
                if (e + u < D) {
                    atomicAdd(&g_acc[D * D + (e + u) * D + jp], acc0[u]);
                    atomicAdd(&g_acc[D * D + (e + u) * D + jp + 1], acc1[u]);
                }
            }
        }
    }
    grid_sync();

    // ---------------- Phase 3: fc2 + softmax -------------------------------
    for (int e = lid; e < D; e += NLANE) {
        float p[OUTC] = {0.f, 0.f, 0.f, 0.f};
        #pragma unroll
        for (int tq = 0; tq < 3; ++tq) {
            int j = ltid + tq * 128;
            if (j < D) {
                float hv = fmaxf(g_acc[D * D + e * D + j] + b1[j], 0.f);
                #pragma unroll
                for (int o = 0; o < OUTC; ++o)
                    p[o] = fmaf(hv, w2[o * D + j], p[o]);
            }
        }
        #pragma unroll
        for (int off = 16; off > 0; off >>= 1) {
            #pragma unroll
            for (int o = 0; o < OUTC; ++o)
                p[o] += __shfl_xor_sync(0xFFFFFFFFu, p[o], off);
        }
        const int w = ltid >> 5, li = ltid & 31;
        LBAR(barid);                    // protect red reuse
        if (li == 0) {
            #pragma unroll
            for (int o = 0; o < OUTC; ++o) L->red[w][o] = p[o];
        }
        LBAR(barid);
        if (ltid == 0) {
            float logits[OUTC];
            #pragma unroll
            for (int o = 0; o < OUTC; ++o)
                logits[o] = L->red[0][o] + L->red[1][o] + L->red[2][o]
                          + L->red[3][o] + b2[o];
            float m = fmaxf(fmaxf(logits[0], logits[1]), fmaxf(logits[2], logits[3]));
            float es[OUTC], ssum = 0.f;
            #pragma unroll
            for (int o = 0; o < OUTC; ++o) { es[o] = expf(logits[o] - m); ssum += es[o]; }
            float inv = 1.f / ssum;
            #pragma unroll
            for (int o = 0; o < OUTC; ++o) out[e * OUTC + o] = es[o] * inv;
        }
    }
}

// ---------------------------------------------------------------------------
// Launch: ONE kernel node.
// Inputs: x1, x2 (i32 [512*512]); emb1, emb2 (f32 [32000*300]);
// w1 (f32 [300*300]); b1 (f32 [300]); w2 (f32 [4*300]); b2 (f32 [4]).
// Output: f32 [300*4].
// ---------------------------------------------------------------------------
extern "C" void kernel_launch(void* const* d_in, const int* in_sizes, int n_in,
                              void* d_out, int out_size) {
    const int*   x1   = (const int*)  d_in[0];
    const int*   x2   = (const int*)  d_in[1];
    const float* emb1 = (const float*)d_in[2];
    const float* emb2 = (const float*)d_in[3];
    const float* w1   = (const float*)d_in[4];
    const float* b1   = (const float*)d_in[5];
    const float* w2   = (const float*)d_in[6];
    const float* b2   = (const float*)d_in[7];
    float* out = (float*)d_out;

    matposer_kernel<<<NBLK, NTHR>>>(x1, x2, emb1, emb2, w1, b1, w2, b2, out);
}

// round 16
// speedup vs baseline: 2.5253x; 2.5253x over previous
#include <cuda_runtime.h>
#include <math.h>

// D_MODEL=300, L=512, B=512, OUT=4.
// diag[e,i] = fmap[i,i,e] = sum_l e2[i,l,i] * e1[i,l,e], i in [0,300)
// Split:  diag[e,i] = scale * sum_l s[i,l]*emb1[x1[i,l]][e]      (term1, gather)
//                   +          sum_l s[i,l]*pe[l][e]             (combine, GEMM)
// with    s[i,l] = emb2[x2[i,l]][i]*scale + pe[l][i]
// Accumulation via atomicAdd into one zeroed buffer; PDL-chained launches.
// (R12 base = best measured; combine DKZ 4->8, fc1 HKZ 5->10.)

#define D     300
#define LSEQ  512
#define OUTC  4
#define NCH   4     // term1 l-split
#define CHUNK 128
#define DKZ   8     // combine K-split (64 per block)
#define HKZ   10    // fc1 K-split
#define KT1   30    // fc1 K per block (10*30=300)

__device__ float g_pe[LSEQ * D];          // [l][d]
__device__ float g_s[D * LSEQ];           // [i][l]
__device__ float g_acc[2 * D * D];        // [0:D*D) diag [e][i]; [D*D:) hidden [e][j]

#define G_DIAG (g_acc)
#define G_HACC (g_acc + D * D)

#define GDC_LAUNCH() asm volatile("griddepcontrol.launch_dependents;")
#define GDC_WAIT()   asm volatile("griddepcontrol.wait;" ::: "memory")

// ---------------------------------------------------------------------------
// Kernel A: zero the accumulator.
// ---------------------------------------------------------------------------
__global__ void zero_kernel() {
    int idx = blockIdx.x * blockDim.x + threadIdx.x;   // float4 index
    if (idx < (2 * D * D) / 4)
        reinterpret_cast<float4*>(g_acc)[idx] = make_float4(0.f, 0.f, 0.f, 0.f);
}

// ---------------------------------------------------------------------------
// Kernel B: positional encoding (float32, matches jnp). Fires dependents at
// entry so term1 runs fully concurrent.
// ---------------------------------------------------------------------------
__global__ void pe_kernel() {
    GDC_LAUNCH();
    int idx = blockIdx.x * blockDim.x + threadIdx.x;
    if (idx >= LSEQ * D) return;
    int l = idx / D;
    int d = idx % D;
    int k = d >> 1;
    const float coef = -9.210340371976184f / (float)D;   // -ln(10000)/300
    float divv = expf((float)(2 * k) * coef);
    float ang  = (float)l * divv;
    g_pe[idx] = (d & 1) ? cosf(ang) : sinf(ang);
}

// ---------------------------------------------------------------------------
// Kernel C: term1. One block per (i, l-chunk of 128). grid (4,300).
// Computes pe[l][i] INLINE (no dependence on pe_kernel output).
// Epilogue: wait(pe done) -> launch_dependents -> atomicAdd into G_DIAG.
// ---------------------------------------------------------------------------
__global__ __launch_bounds__(320) void term1_kernel(
    const int*   __restrict__ x1,
    const int*   __restrict__ x2,
    const float* __restrict__ emb1,
    const float* __restrict__ emb2)
{
    const int chunk = blockIdx.x;          // 0..3
    const int i     = blockIdx.y;          // 0..299
    const int tid   = threadIdx.x;
    const float scale = 17.320508075688775f;  // sqrt(300)
    const float coef  = -9.210340371976184f / (float)D;

    __shared__ float s_sh[CHUNK];
    __shared__ int   r1_sh[CHUNK];

    if (tid < CHUNK) {
        int l  = chunk * CHUNK + tid;
        int t2 = x2[i * LSEQ + l];
        // inline pe[l][i]
        float divv = expf((float)(2 * (i >> 1)) * coef);
        float ang  = (float)l * divv;
        float pev  = (i & 1) ? cosf(ang) : sinf(ang);
        float sv = fmaf(emb2[t2 * D + i], scale, pev);
        s_sh[tid] = sv;
        g_s[i * LSEQ + l] = sv;
        r1_sh[tid] = x1[i * LSEQ + l] * D;
    }
    __syncthreads();

    float r = 0.f;
    if (tid < D) {
        const int e = tid;
        float acc[8];
        #pragma unroll
        for (int u = 0; u < 8; ++u) acc[u] = 0.f;
        #pragma unroll 2
        for (int l = 0; l < CHUNK; l += 8) {
            #pragma unroll
            for (int u = 0; u < 8; ++u)
                acc[u] = fmaf(s_sh[l + u], emb1[r1_sh[l + u] + e], acc[u]);
        }
        r = ((acc[0] + acc[1]) + (acc[2] + acc[3]))
          + ((acc[4] + acc[5]) + (acc[6] + acc[7]));
    }

    GDC_WAIT();      // ensure pe_kernel done before dependents may launch
    GDC_LAUNCH();

    if (tid < D)
        atomicAdd(&G_DIAG[tid * D + i], scale * r);
}

// ---------------------------------------------------------------------------
// Kernel D: combine (term2 GEMM), atomicAdd into G_DIAG.
//   G_DIAG[e][i] += sum_{l in 64-window kz} s[i,l]*pe[l][e]
// grid (10,10,8), 128 threads (16,8). Thread tile 4e x 2i.
// pe tile staged PRE-WAIT (pe complete before term1 dependents fire).
// ---------------------------------------------------------------------------
__global__ __launch_bounds__(128) void combine_kernel()
{
    __shared__ float sh_st[64][34];    // [k][i_local]
    __shared__ float sh_pe[64][36];    // [k][e_local], 16B-aligned rows

    const int tx  = threadIdx.x;       // 0..15 -> i = i0 + 2*tx + {0,1}
    const int ty  = threadIdx.y;       // 0..7  -> e = e0 + 4*ty + {0..3}
    const int lin = ty * 16 + tx;
    const int e0  = blockIdx.x * 32;
    const int i0  = blockIdx.y * 32;
    const int kb  = blockIdx.z * 64;

    // PRE-WAIT: stage pe tile (depends only on pe_kernel, already complete)
    #pragma unroll
    for (int t = 0; t < 4; ++t) {
        int idx = lin + t * 128;           // 0..511
        int row = idx >> 3;                // 0..63 (k_local)
        int cc  = (idx & 7) * 4;           // 0..28
        int e   = e0 + cc;
        float4 v = make_float4(0.f, 0.f, 0.f, 0.f);
        if (e <= D - 4)
            v = *reinterpret_cast<const float4*>(g_pe + (kb + row) * D + e);
        *reinterpret_cast<float4*>(&sh_pe[row][cc]) = v;
    }

    GDC_WAIT();      // term1 complete: g_s valid
    GDC_LAUNCH();    // let fc1 start staging w1

    // stage s tile transposed: 32 i-rows x 64 k
    #pragma unroll
    for (int t = 0; t < 4; ++t) {
        int idx = lin + t * 128;           // 0..511
        int row = idx >> 4;                // 0..31 (i_local)
        int kk  = (idx & 15) * 4;          // 0..60
        float4 v = make_float4(0.f, 0.f, 0.f, 0.f);
        int ii = i0 + row;
        if (ii < D)
            v = *reinterpret_cast<const float4*>(g_s + ii * LSEQ + kb + kk);
        sh_st[kk][row] = v.x; sh_st[kk + 1][row] = v.y;
        sh_st[kk + 2][row] = v.z; sh_st[kk + 3][row] = v.w;
    }
    __syncthreads();

    float acc0[4] = {0.f, 0.f, 0.f, 0.f};   // i = ip
    float acc1[4] = {0.f, 0.f, 0.f, 0.f};   // i = ip+1
    #pragma unroll 4
    for (int k = 0; k < 64; ++k) {
        float2 sv = *reinterpret_cast<const float2*>(&sh_st[k][2 * tx]);
        float4 pv = *reinterpret_cast<const float4*>(&sh_pe[k][4 * ty]);
        acc0[0] = fmaf(sv.x, pv.x, acc0[0]);
        acc0[1] = fmaf(sv.x, pv.y, acc0[1]);
        acc0[2] = fmaf(sv.x, pv.z, acc0[2]);
        acc0[3] = fmaf(sv.x, pv.w, acc0[3]);
        acc1[0] = fmaf(sv.y, pv.x, acc1[0]);
        acc1[1] = fmaf(sv.y, pv.y, acc1[1]);
        acc1[2] = fmaf(sv.y, pv.z, acc1[2]);
        acc1[3] = fmaf(sv.y, pv.w, acc1[3]);
    }

    const int ip = i0 + 2 * tx;
    const int e  = e0 + 4 * ty;
    if (ip < D) {
        #pragma unroll
        for (int u = 0; u < 4; ++u) {
            if (e + u < D) {
                atomicAdd(&G_DIAG[(e + u) * D + ip], acc0[u]);
                atomicAdd(&G_DIAG[(e + u) * D + ip + 1], acc1[u]);
            }
        }
    }
}

// ---------------------------------------------------------------------------
// Kernel E: FC1, atomicAdd into G_HACC.
//   G_HACC[e][j] += sum_{k in 30-window} diag[e][k] * w1[j][k]
// grid (10,10,10), 128 threads. w1 staged PRE-WAIT (float2 granulated).
// k-major smem tiles. Thread tile 4e x 2j.
// ---------------------------------------------------------------------------
__global__ __launch_bounds__(128) void fc1_kernel(
    const float* __restrict__ w1)
{
    __shared__ float sat[KT1][36];
    __shared__ float sbt[KT1][36];

    const int tx  = threadIdx.x;        // 0..15 -> j
    const int ty  = threadIdx.y;        // 0..7  -> e
    const int lin = ty * 16 + tx;
    const int j0  = blockIdx.x * 32;
    const int e0  = blockIdx.y * 32;
    const int kb  = blockIdx.z * KT1;

    // PRE-WAIT: stage w1 tile (32 rows x 15 float2)
    for (int idx = lin; idx < 32 * 15; idx += 128) {
        int row = idx / 15;
        int kk  = (idx % 15) * 2;
        int k   = kb + kk;                  // max 270+28+1 = 299
        float2 vb = make_float2(0.f, 0.f);
        if (j0 + row < D)
            vb = *reinterpret_cast<const float2*>(w1 + (j0 + row) * D + k);
        sbt[kk][row] = vb.x; sbt[kk + 1][row] = vb.y;
    }

    GDC_WAIT();      // combine complete: G_DIAG final
    GDC_LAUNCH();    // let fc2 preload w2/b1

    for (int idx = lin; idx < 32 * 15; idx += 128) {
        int row = idx / 15;
        int kk  = (idx % 15) * 2;
        int k   = kb + kk;
        float2 va = make_float2(0.f, 0.f);
        if (e0 + row < D)
            va = *reinterpret_cast<const float2*>(G_DIAG + (e0 + row) * D + k);
        sat[kk][row] = va.x; sat[kk + 1][row] = va.y;
    }
    __syncthreads();

    float acc0[4] = {0.f, 0.f, 0.f, 0.f};
    float acc1[4] = {0.f, 0.f, 0.f, 0.f};
    #pragma unroll 6
    for (int k = 0; k < KT1; ++k) {
        float4 a = *reinterpret_cast<const float4*>(&sat[k][4 * ty]);
        float2 b = *reinterpret_cast<const float2*>(&sbt[k][2 * tx]);
        acc0[0] = fmaf(b.x, a.x, acc0[0]);
        acc0[1] = fmaf(b.x, a.y, acc0[1]);
        acc0[2] = fmaf(b.x, a.z, acc0[2]);
        acc0[3] = fmaf(b.x, a.w, acc0[3]);
        acc1[0] = fmaf(b.y, a.x, acc1[0]);
        acc1[1] = fmaf(b.y, a.y, acc1[1]);
        acc1[2] = fmaf(b.y, a.z, acc1[2]);
        acc1[3] = fmaf(b.y, a.w, acc1[3]);
    }

    const int jp = j0 + 2 * tx;
    const int e  = e0 + 4 * ty;
    if (jp < D) {
        #pragma unroll
        for (int u = 0; u < 4; ++u) {
            if (e + u < D) {
                atomicAdd(&G_HACC[(e + u) * D + jp], acc0[u]);
                atomicAdd(&G_HACC[(e + u) * D + jp + 1], acc1[u]);
            }
        }
    }
}

// ---------------------------------------------------------------------------
// Kernel F: FC2 + softmax. One block per e-row. w2/b1 preloaded PRE-WAIT.
// ---------------------------------------------------------------------------
__global__ __launch_bounds__(128) void fc2_kernel(
    const float* __restrict__ b1,
    const float* __restrict__ w2,
    const float* __restrict__ b2,
    float*       __restrict__ out)
{
    const int e   = blockIdx.x;
    const int tid = threadIdx.x;

    float wv[3][OUTC];
    float bv[3];
    #pragma unroll
    for (int t = 0; t < 3; ++t) {
        int j = tid + t * 128;
        if (j < D) {
            bv[t] = b1[j];
            #pragma unroll
            for (int o = 0; o < OUTC; ++o) wv[t][o] = w2[o * D + j];
        } else {
            bv[t] = 0.f;
            #pragma unroll
            for (int o = 0; o < OUTC; ++o) wv[t][o] = 0.f;
        }
    }

    GDC_WAIT();      // fc1 complete: G_HACC final

    float p[OUTC] = {0.f, 0.f, 0.f, 0.f};
    #pragma unroll
    for (int t = 0; t < 3; ++t) {
        int j = tid + t * 128;
        if (j < D) {
            float hv = fmaxf(G_HACC[e * D + j] + bv[t], 0.f);
            #pragma unroll
            for (int o = 0; o < OUTC; ++o)
                p[o] = fmaf(hv, wv[t][o], p[o]);
        }
    }

    #pragma unroll
    for (int off = 16; off > 0; off >>= 1) {
        #pragma unroll
        for (int o = 0; o < OUTC; ++o)
            p[o] += __shfl_xor_sync(0xFFFFFFFFu, p[o], off);
    }

    __shared__ float red[4][OUTC];
    const int wid = tid >> 5, lid = tid & 31;
    if (lid == 0) {
        #pragma unroll
        for (int o = 0; o < OUTC; ++o) red[wid][o] = p[o];
    }
    __syncthreads();

    if (tid == 0) {
        float logits[OUTC];
        #pragma unroll
        for (int o = 0; o < OUTC; ++o)
            logits[o] = red[0][o] + red[1][o] + red[2][o] + red[3][o] + b2[o];
        float m = fmaxf(fmaxf(logits[0], logits[1]), fmaxf(logits[2], logits[3]));
        float es[OUTC], ssum = 0.f;
        #pragma unroll
        for (int o = 0; o < OUTC; ++o) { es[o] = expf(logits[o] - m); ssum += es[o]; }
        float inv = 1.f / ssum;
        #pragma unroll
        for (int o = 0; o < OUTC; ++o) out[e * OUTC + o] = es[o] * inv;
    }
}

// ---------------------------------------------------------------------------
// Launch chain (PDL): zero -> pe -> term1 -> combine -> fc1 -> fc2.
// Inputs: x1, x2 (i32 [512*512]); emb1, emb2 (f32 [32000*300]);
// w1 (f32 [300*300]); b1 (f32 [300]); w2 (f32 [4*300]); b2 (f32 [4]).
// Output: f32 [300*4].
// ---------------------------------------------------------------------------
extern "C" void kernel_launch(void* const* d_in, const int* in_sizes, int n_in,
                              void* d_out, int out_size) {
    const int*   x1   = (const int*)  d_in[0];
    const int*   x2   = (const int*)  d_in[1];
    const float* emb1 = (const float*)d_in[2];
    const float* emb2 = (const float*)d_in[3];
    const float* w1   = (const float*)d_in[4];
    const float* b1   = (const float*)d_in[5];
    const float* w2   = (const float*)d_in[6];
    const float* b2   = (const float*)d_in[7];
    float* out = (float*)d_out;

    cudaLaunchAttribute pss[1];
    pss[0].id = cudaLaunchAttributeProgrammaticStreamSerialization;
    pss[0].val.programmaticStreamSerializationAllowed = 1;

    zero_kernel<<<(2 * D * D / 4 + 255) / 256, 256>>>();
    pe_kernel<<<(LSEQ * D + 255) / 256, 256>>>();

    {   // term1 (PSS — launches as soon as pe enters)
        cudaLaunchConfig_t cfg = {};
        cfg.gridDim = dim3(NCH, D); cfg.blockDim = dim3(320);
        cfg.attrs = pss; cfg.numAttrs = 1;
        cudaLaunchKernelEx(&cfg, term1_kernel, x1, x2, emb1, emb2);
    }
    {   // combine (PSS)
        cudaLaunchConfig_t cfg = {};
        cfg.gridDim = dim3(10, 10, DKZ); cfg.blockDim = dim3(16, 8);
        cfg.attrs = pss; cfg.numAttrs = 1;
        cudaLaunchKernelEx(&cfg, combine_kernel);
    }
    {   // fc1 (PSS)
        cudaLaunchConfig_t cfg = {};
        cfg.gridDim = dim3(10, 10, HKZ); cfg.blockDim = dim3(16, 8);
        cfg.attrs = pss; cfg.numAttrs = 1;
        cudaLaunchKernelEx(&cfg, fc1_kernel, w1);
    }
    {   // fc2 (PSS)
        cudaLaunchConfig_t cfg = {};
        cfg.gridDim = dim3(D); cfg.blockDim = dim3(128);
        cfg.attrs = pss; cfg.numAttrs = 1;
        cudaLaunchKernelEx(&cfg, fc2_kernel, b1, w2, b2, out);
    }
}